// round 5
// baseline (speedup 1.0000x reference)
#include <cuda_runtime.h>
#include <math.h>
#include <stdint.h>

#define Bn 16
#define Sn 512
#define Dn 768
#define Hn 8
#define DKn 96

// ======================= static scratch =======================
__device__ float g_q[Bn * Sn * Dn];
__device__ float g_k[Bn * Sn * Dn];
__device__ float g_ax[Bn * Sn * Dn];
__device__ float g_h0[Bn * Sn * Dn];
__device__ float g_h1[Bn * Sn * Dn];
__device__ float g_denom[Bn * Sn];
__device__ float g_pool[Bn * 2 * Dn];
__device__ float g_gc[Bn * Dn];
__device__ float g_gate[Bn * Dn];

// ======================= helpers =======================
__device__ __forceinline__ void tf32_split1(float x, float& h, float& l) {
    asm("cvt.rna.tf32.f32 %0, %1;" : "=f"(h) : "f"(x));
    asm("cvt.rna.tf32.f32 %0, %1;" : "=f"(l) : "f"(x - h));
}
__device__ __forceinline__ void split4(const float4 v, float4& h, float4& l) {
    tf32_split1(v.x, h.x, l.x);
    tf32_split1(v.y, h.y, l.y);
    tf32_split1(v.z, h.z, l.z);
    tf32_split1(v.w, h.w, l.w);
}
__device__ __forceinline__ void mma_tf32(float* c, const uint32_t* a, const uint32_t* b) {
    asm volatile(
        "mma.sync.aligned.m16n8k8.row.col.f32.tf32.tf32.f32 "
        "{%0,%1,%2,%3}, {%4,%5,%6,%7}, {%8,%9}, {%0,%1,%2,%3};"
        : "+f"(c[0]), "+f"(c[1]), "+f"(c[2]), "+f"(c[3])
        : "r"(a[0]), "r"(a[1]), "r"(a[2]), "r"(a[3]), "r"(b[0]), "r"(b[1]));
}

// ======================= tensor-core GEMM =======================
// C[bz] = act((A[bz][M,K] @ B[bz][K,N] + bias) / denom), split-tf32 (3 MMA terms).
// CTA tile 256x128, BK=16, 256 threads = 8 warps in 4(M) x 2(N) grid, 64x64 per warp.
// hi/lo tf32 planes pre-split at staging (no cvt in mainloop). Double-buffered smem.
// Requires M%256==0, N%128==0, K%16==0.
#define AP 20
#define BP 132
#define APL (256 * AP)
#define BPL (16 * BP)
#define AOFF(buf, pl) (((buf) * 2 + (pl)) * APL)
#define BOFF(buf, pl) (4 * APL + ((buf) * 2 + (pl)) * BPL)
#define TC_SMEM ((4 * APL + 4 * BPL) * 4)

template <int RELU, int DIV, int BIAS>
__global__ void __launch_bounds__(256) tc_gemm(
    const float* __restrict__ A, const float* __restrict__ B,
    const float* __restrict__ bias, const float* __restrict__ denom,
    float* __restrict__ C, int N, int K,
    long long strA, long long strB, long long strC)
{
    extern __shared__ float sm[];
    const int tid = threadIdx.x;
    const int lane = tid & 31, wid = tid >> 5;
    const int gid = lane >> 2, tig = lane & 3;
    const int wm = wid >> 1, wn = wid & 1;
    const int row0 = blockIdx.y * 256, col0 = blockIdx.x * 128;
    const int bz = blockIdx.z;

    A += (long long)bz * strA;
    B += (long long)bz * strB;
    C += (long long)bz * strC;

    const float* Ar = A + (long long)(row0 + tid) * K;      // this thread's A row
    const int bk = tid & 15, bn = (tid >> 4) * 8;           // B staging coords
    const float* Br = B + (long long)bk * N + col0 + bn;

    const int nt = K >> 4;
    float4 pA[4], pB[2];

    float acc[4][8][4];
#pragma unroll
    for (int i = 0; i < 4; i++)
#pragma unroll
        for (int j = 0; j < 8; j++)
#pragma unroll
            for (int r = 0; r < 4; r++) acc[i][j][r] = 0.f;

#define LOADP(cc) do {                                                          \
    _Pragma("unroll")                                                           \
    for (int j_ = 0; j_ < 4; j_++)                                              \
        pA[j_] = *(const float4*)(Ar + (cc) * 16 + 4 * j_);                     \
    pB[0] = *(const float4*)(Br + (long long)(cc) * 16 * N);                    \
    pB[1] = *(const float4*)(Br + (long long)(cc) * 16 * N + 4);                \
} while (0)

#define STOREP(bb) do {                                                         \
    float* ah_ = sm + AOFF(bb, 0) + tid * AP;                                   \
    float* al_ = sm + AOFF(bb, 1) + tid * AP;                                   \
    _Pragma("unroll")                                                           \
    for (int j_ = 0; j_ < 4; j_++) {                                            \
        float4 h4_, l4_;                                                        \
        split4(pA[j_], h4_, l4_);                                               \
        *(float4*)(ah_ + 4 * j_) = h4_;                                         \
        *(float4*)(al_ + 4 * j_) = l4_;                                         \
    }                                                                           \
    {                                                                           \
        float* bh_ = sm + BOFF(bb, 0) + bk * BP + bn;                           \
        float* bl_ = sm + BOFF(bb, 1) + bk * BP + bn;                           \
        float4 h0_, l0_, h1_, l1_;                                              \
        split4(pB[0], h0_, l0_);                                                \
        split4(pB[1], h1_, l1_);                                                \
        *(float4*)bh_ = h0_;  *(float4*)(bh_ + 4) = h1_;                        \
        *(float4*)bl_ = l0_;  *(float4*)(bl_ + 4) = l1_;                        \
    }                                                                           \
} while (0)

    LOADP(0);
    STOREP(0);
    __syncthreads();

    for (int c = 0; c < nt; c++) {
        const int buf = c & 1;
        if (c + 1 < nt) LOADP(c + 1);

        const uint32_t* AH = (const uint32_t*)(sm + AOFF(buf, 0));
        const uint32_t* AL = (const uint32_t*)(sm + AOFF(buf, 1));
        const uint32_t* BH = (const uint32_t*)(sm + BOFF(buf, 0));
        const uint32_t* BL = (const uint32_t*)(sm + BOFF(buf, 1));

#pragma unroll
        for (int kk = 0; kk < 2; kk++) {
            const int kb = kk * 8;
            uint32_t ah[4][4], al[4][4];
#pragma unroll
            for (int i = 0; i < 4; i++) {
                const int m = wm * 64 + i * 16 + gid;
                ah[i][0] = AH[m * AP + kb + tig];
                ah[i][1] = AH[(m + 8) * AP + kb + tig];
                ah[i][2] = AH[m * AP + kb + tig + 4];
                ah[i][3] = AH[(m + 8) * AP + kb + tig + 4];
                al[i][0] = AL[m * AP + kb + tig];
                al[i][1] = AL[(m + 8) * AP + kb + tig];
                al[i][2] = AL[m * AP + kb + tig + 4];
                al[i][3] = AL[(m + 8) * AP + kb + tig + 4];
            }
#pragma unroll
            for (int j = 0; j < 8; j++) {
                const int n = wn * 64 + j * 8 + gid;
                uint32_t bh[2], bl[2];
                bh[0] = BH[(kb + tig) * BP + n];
                bh[1] = BH[(kb + tig + 4) * BP + n];
                bl[0] = BL[(kb + tig) * BP + n];
                bl[1] = BL[(kb + tig + 4) * BP + n];
#pragma unroll
                for (int i = 0; i < 4; i++) mma_tf32(acc[i][j], ah[i], bh);
#pragma unroll
                for (int i = 0; i < 4; i++) mma_tf32(acc[i][j], ah[i], bl);
#pragma unroll
                for (int i = 0; i < 4; i++) mma_tf32(acc[i][j], al[i], bh);
            }
        }
        if (c + 1 < nt) STOREP(buf ^ 1);
        __syncthreads();
    }

    // epilogue
#pragma unroll
    for (int i = 0; i < 4; i++) {
        const int r0 = row0 + wm * 64 + i * 16 + gid;
        float inv0 = 1.f, inv1 = 1.f;
        if (DIV) { inv0 = 1.f / denom[r0]; inv1 = 1.f / denom[r0 + 8]; }
#pragma unroll
        for (int j = 0; j < 8; j++) {
            const int nc = col0 + wn * 64 + j * 8 + 2 * tig;
            float bx = 0.f, by = 0.f;
            if (BIAS) { const float2 bb = *(const float2*)(bias + nc); bx = bb.x; by = bb.y; }
            float o0 = acc[i][j][0] + bx, o1 = acc[i][j][1] + by;
            float o2 = acc[i][j][2] + bx, o3 = acc[i][j][3] + by;
            if (DIV) { o0 *= inv0; o1 *= inv0; o2 *= inv1; o3 *= inv1; }
            if (RELU) {
                o0 = fmaxf(o0, 0.f); o1 = fmaxf(o1, 0.f);
                o2 = fmaxf(o2, 0.f); o3 = fmaxf(o3, 0.f);
            }
            *(float2*)(C + (long long)r0 * N + nc) = make_float2(o0, o1);
            *(float2*)(C + (long long)(r0 + 8) * N + nc) = make_float2(o2, o3);
        }
    }
}

// ======================= fused attention (unchanged, proven) =======================
__global__ void __launch_bounds__(512, 2) attn_kernel(
    const float* __restrict__ qm, const float* __restrict__ km,
    const int* __restrict__ tok, const float* __restrict__ rel_emb,
    float* __restrict__ adj, float* __restrict__ denom)
{
    __shared__ __align__(16) float sQ[8][Dn];
    __shared__ __align__(16) float sQm[8][DKn];
    __shared__ float sR[8][257];
    __shared__ float sRed[16][8];
    __shared__ float sB[8];
    __shared__ int sTokQ[8];

    const int tid = threadIdx.x;
    const int b = blockIdx.x >> 6;
    const int q0 = (blockIdx.x & 63) * 8;
    const long long qbase = ((long long)b * Sn + q0) * Dn;

    for (int e = tid; e < 8 * Dn; e += 512) ((float*)sQ)[e] = qm[qbase + e];
    if (tid < 8) sTokQ[tid] = tok[b * Sn + q0 + tid];
    __syncthreads();

    for (int e = tid; e < 8 * DKn; e += 512) {
        const int qq = e / DKn, d = e % DKn;
        float s = 0.f;
#pragma unroll
        for (int h = 0; h < Hn; h++) s += sQ[qq][h * DKn + d];
        sQm[qq][d] = s * 0.125f;
    }
    __syncthreads();

    for (int e = tid; e < 8 * 257; e += 512) {
        const int qq = e / 257, j = e % 257;
        const float4* rp = (const float4*)(rel_emb + j * DKn);
        const float4* qp = (const float4*)sQm[qq];
        float s = 0.f;
#pragma unroll
        for (int d4 = 0; d4 < DKn / 4; d4++) {
            float4 rv = rp[d4], qv = qp[d4];
            s += rv.x * qv.x + rv.y * qv.y + rv.z * qv.z + rv.w * qv.w;
        }
        sR[qq][j] = s;
    }
    __syncthreads();

    const int kcol = tid;
    const bool kz = (tok[b * Sn + kcol] == 0);
    const float4* krow = (const float4*)(km + ((long long)b * Sn + kcol) * Dn);
    const float scale = 0.10206207261596577f;
    const int lane = tid & 31, wid = tid >> 5;

    float padj[8];
#pragma unroll
    for (int qq = 0; qq < 8; qq++) padj[qq] = 0.f;

    for (int h = 0; h < Hn; h++) {
        float sc[8];
#pragma unroll
        for (int qq = 0; qq < 8; qq++) sc[qq] = 0.f;
        const float4* kh = krow + h * (DKn / 4);
#pragma unroll
        for (int d4 = 0; d4 < DKn / 4; d4++) {
            const float4 kv = kh[d4];
#pragma unroll
            for (int qq = 0; qq < 8; qq++) {
                const float4 qv = *(const float4*)&sQ[qq][h * DKn + d4 * 4];
                sc[qq] += kv.x * qv.x + kv.y * qv.y + kv.z * qv.z + kv.w * qv.w;
            }
        }
#pragma unroll
        for (int qq = 0; qq < 8; qq++) {
            int dist = kcol - (q0 + qq);
            dist = min(max(dist, -128), 128) + 128;
            const float s = (sc[qq] + sR[qq][dist]) * scale;
            sc[qq] = kz ? -1e9f : s;
        }
        float red[8];
#pragma unroll
        for (int qq = 0; qq < 8; qq++) red[qq] = sc[qq];
#pragma unroll
        for (int off = 16; off > 0; off >>= 1)
#pragma unroll
            for (int qq = 0; qq < 8; qq++)
                red[qq] = fmaxf(red[qq], __shfl_xor_sync(0xffffffffu, red[qq], off));
        if (lane == 0)
#pragma unroll
            for (int qq = 0; qq < 8; qq++) sRed[wid][qq] = red[qq];
        __syncthreads();
        if (tid < 8) {
            float v = sRed[0][tid];
#pragma unroll
            for (int w = 1; w < 16; w++) v = fmaxf(v, sRed[w][tid]);
            sB[tid] = v;
        }
        __syncthreads();
        float ex[8];
#pragma unroll
        for (int qq = 0; qq < 8; qq++) ex[qq] = expf(sc[qq] - sB[qq]);
#pragma unroll
        for (int qq = 0; qq < 8; qq++) red[qq] = ex[qq];
#pragma unroll
        for (int off = 16; off > 0; off >>= 1)
#pragma unroll
            for (int qq = 0; qq < 8; qq++)
                red[qq] += __shfl_xor_sync(0xffffffffu, red[qq], off);
        if (lane == 0)
#pragma unroll
            for (int qq = 0; qq < 8; qq++) sRed[wid][qq] = red[qq];
        __syncthreads();
        if (tid < 8) {
            float v = 0.f;
#pragma unroll
            for (int w = 0; w < 16; w++) v += sRed[w][tid];
            sB[tid] = v;
        }
        __syncthreads();
#pragma unroll
        for (int qq = 0; qq < 8; qq++) padj[qq] += (ex[qq] / sB[qq]) * 0.125f;
        __syncthreads();
    }

    float rowv[8];
#pragma unroll
    for (int qq = 0; qq < 8; qq++) {
        float v = padj[qq];
        if (kcol == q0 + qq) v = 1.0f;
        if (sTokQ[qq] == 0) v = 0.0f;
        rowv[qq] = v;
        adj[((long long)b * Sn + q0 + qq) * Sn + kcol] = v;
    }
    float red[8];
#pragma unroll
    for (int qq = 0; qq < 8; qq++) red[qq] = rowv[qq];
#pragma unroll
    for (int off = 16; off > 0; off >>= 1)
#pragma unroll
        for (int qq = 0; qq < 8; qq++)
            red[qq] += __shfl_xor_sync(0xffffffffu, red[qq], off);
    if (lane == 0)
#pragma unroll
        for (int qq = 0; qq < 8; qq++) sRed[wid][qq] = red[qq];
    __syncthreads();
    if (tid < 8) {
        float v = 0.f;
#pragma unroll
        for (int w = 0; w < 16; w++) v += sRed[w][tid];
        denom[b * Sn + q0 + tid] = v + 1.0f;
    }
}

// ======================= small kernels =======================
__global__ void combine_kernel(const float* __restrict__ h0, const float* __restrict__ h1,
                               const float* __restrict__ sw, float* __restrict__ out)
{
    const int i = blockIdx.x * 256 + threadIdx.x;
    const float s0 = sw[0], s1 = sw[1];
    const float m = fmaxf(s0, s1);
    const float e0 = expf(s0 - m), e1 = expf(s1 - m);
    const float inv = 1.f / (e0 + e1);
    out[i] = (e0 * inv) * h0[i] + (e1 * inv) * h1[i];
}

__global__ void pool_kernel(const float* __restrict__ x, float* __restrict__ pool)
{
    const int b = blockIdx.y;
    const int d = blockIdx.x * 128 + threadIdx.x;
    const float* xp = x + (long long)b * Sn * Dn + d;
    float sm = 0.f, mx = -3.402823466e38f;
    for (int s = 0; s < Sn; s++) {
        const float v = xp[(long long)s * Dn];
        sm += v;
        mx = fmaxf(mx, v);
    }
    pool[b * (2 * Dn) + d] = sm * (1.f / Sn);
    pool[b * (2 * Dn) + Dn + d] = mx;
}

template <int ACT>
__global__ void rowmat_kernel(const float* __restrict__ in, const float* __restrict__ W,
                              const float* __restrict__ bias, float* __restrict__ out,
                              int K, int N)
{
    __shared__ float sIn[2 * Dn];
    const int b = blockIdx.y;
    const int n = blockIdx.x * 128 + threadIdx.x;
    for (int e = threadIdx.x; e < K; e += 128) sIn[e] = in[b * K + e];
    __syncthreads();
    float acc = bias[n];
#pragma unroll 4
    for (int k = 0; k < K; k++) acc += sIn[k] * W[(long long)k * N + n];
    if (ACT) acc = 1.f / (1.f + expf(-acc));
    out[b * N + n] = acc;
}

__global__ void final_kernel(float* __restrict__ x, const float* __restrict__ gate,
                             const float* __restrict__ gc)
{
    const int i = blockIdx.x * 256 + threadIdx.x;
    const int d = i % Dn;
    const int b = i / (Sn * Dn);
    x[i] += gate[b * Dn + d] * gc[b * Dn + d];
}

// ======================= launch =======================
extern "C" void kernel_launch(void* const* d_in, const int* in_sizes, int n_in,
                              void* d_out, int out_size)
{
    int o = (n_in >= 3 && in_sizes[2] == 1) ? 1 : 0;
    const float* inputs = (const float*)d_in[0];
    const int*   tok    = (const int*)d_in[1];
    const float* Wq  = (const float*)d_in[2 + o];
    const float* bq  = (const float*)d_in[3 + o];
    const float* Wk  = (const float*)d_in[4 + o];
    const float* bk  = (const float*)d_in[5 + o];
    const float* rel = (const float*)d_in[6 + o];
    const float* W0  = (const float*)d_in[7 + o];
    const float* b0  = (const float*)d_in[8 + o];
    const float* W1  = (const float*)d_in[9 + o];
    const float* b1  = (const float*)d_in[10 + o];
    const float* scw = (const float*)d_in[11 + o];
    const float* Wf  = (const float*)d_in[12 + o];
    const float* bf  = (const float*)d_in[13 + o];
    const float* Wfc = (const float*)d_in[14 + o];
    const float* bfc = (const float*)d_in[15 + o];
    const float* Wg  = (const float*)d_in[16 + o];
    const float* bg  = (const float*)d_in[17 + o];

    float* out = (float*)d_out;                      // (B,S,D)
    float* adj = out + (size_t)Bn * Sn * Dn;         // (B,S,S)

    float *q, *k, *ax, *h0, *h1, *den, *pool, *gc, *gate;
    cudaGetSymbolAddress((void**)&q, g_q);
    cudaGetSymbolAddress((void**)&k, g_k);
    cudaGetSymbolAddress((void**)&ax, g_ax);
    cudaGetSymbolAddress((void**)&h0, g_h0);
    cudaGetSymbolAddress((void**)&h1, g_h1);
    cudaGetSymbolAddress((void**)&den, g_denom);
    cudaGetSymbolAddress((void**)&pool, g_pool);
    cudaGetSymbolAddress((void**)&gc, g_gc);
    cudaGetSymbolAddress((void**)&gate, g_gate);

    cudaFuncSetAttribute(tc_gemm<0, 0, 1>, cudaFuncAttributeMaxDynamicSharedMemorySize, TC_SMEM);
    cudaFuncSetAttribute(tc_gemm<0, 0, 0>, cudaFuncAttributeMaxDynamicSharedMemorySize, TC_SMEM);
    cudaFuncSetAttribute(tc_gemm<1, 1, 1>, cudaFuncAttributeMaxDynamicSharedMemorySize, TC_SMEM);

    const dim3 gFlat(Dn / 128, (Bn * Sn) / 256, 1);  // 6 x 32
    const dim3 gBmm(Dn / 128, Sn / 256, Bn);         // 6 x 2 x 16
    const int nElem = Bn * Sn * Dn;

    // Q/K projections
    tc_gemm<0, 0, 1><<<gFlat, 256, TC_SMEM>>>(inputs, Wq, bq, nullptr, q, Dn, Dn, 0, 0, 0);
    tc_gemm<0, 0, 1><<<gFlat, 256, TC_SMEM>>>(inputs, Wk, bk, nullptr, k, Dn, Dn, 0, 0, 0);

    // fused attention -> adj, denom
    attn_kernel<<<Bn * (Sn / 8), 512>>>(q, k, tok, rel, adj, den);

    // GCN layer 0
    tc_gemm<0, 0, 0><<<gBmm, 256, TC_SMEM>>>(adj, inputs, nullptr, nullptr, ax, Dn, Sn,
                                             (long long)Sn * Sn, (long long)Sn * Dn,
                                             (long long)Sn * Dn);
    tc_gemm<1, 1, 1><<<gFlat, 256, TC_SMEM>>>(ax, W0, b0, den, h0, Dn, Dn, 0, 0, 0);

    // GCN layer 1
    tc_gemm<0, 0, 0><<<gBmm, 256, TC_SMEM>>>(adj, h0, nullptr, nullptr, ax, Dn, Sn,
                                             (long long)Sn * Sn, (long long)Sn * Dn,
                                             (long long)Sn * Dn);
    tc_gemm<1, 1, 1><<<gFlat, 256, TC_SMEM>>>(ax, W1, b1, den, h1, Dn, Dn, 0, 0, 0);

    // fusion + Wf -> out
    combine_kernel<<<nElem / 256, 256>>>(h0, h1, scw, ax);
    tc_gemm<0, 0, 1><<<gFlat, 256, TC_SMEM>>>(ax, Wf, bf, nullptr, out, Dn, Dn, 0, 0, 0);

    // global context gating
    pool_kernel<<<dim3(Dn / 128, Bn), 128>>>(out, pool);
    rowmat_kernel<0><<<dim3(Dn / 128, Bn), 128>>>(pool, Wfc, bfc, gc, 2 * Dn, Dn);
    rowmat_kernel<1><<<dim3(Dn / 128, Bn), 128>>>(gc, Wg, bg, gate, Dn, Dn);
    final_kernel<<<(Bn * Sn * Dn) / 256, 256>>>(out, gate, gc);
}

// round 6
// speedup vs baseline: 1.2066x; 1.2066x over previous
#include <cuda_runtime.h>
#include <math.h>
#include <stdint.h>

#define Bn 16
#define Sn 512
#define Dn 768
#define Hn 8
#define DKn 96

// ======================= static scratch =======================
__device__ float g_q[Bn * Sn * Dn];
__device__ float g_k[Bn * Sn * Dn];
__device__ float g_ax[Bn * Sn * Dn];
__device__ float g_h0[Bn * Sn * Dn];
__device__ float g_h1[Bn * Sn * Dn];
__device__ float g_denom[Bn * Sn];
__device__ float g_pool[Bn * 2 * Dn];
__device__ float g_gc[Bn * Dn];
__device__ float g_gate[Bn * Dn];

// ======================= helpers =======================
__device__ __forceinline__ uint32_t smem_to_u32(const void* p) {
    uint32_t a;
    asm("{ .reg .u64 t; cvta.to.shared.u64 t, %1; cvt.u32.u64 %0, t; }" : "=r"(a) : "l"(p));
    return a;
}

#define CP_ASYNC16(dst, src) \
    asm volatile("cp.async.cg.shared.global [%0], [%1], 16;" :: "r"(dst), "l"(src) : "memory")

__device__ __forceinline__ void tf32_split(float x, uint32_t& hi, uint32_t& lo) {
    float h, l;
    asm("cvt.rna.tf32.f32 %0, %1;" : "=f"(h) : "f"(x));
    asm("cvt.rna.tf32.f32 %0, %1;" : "=f"(l) : "f"(x - h));
    hi = __float_as_uint(h);
    lo = __float_as_uint(l);
}

__device__ __forceinline__ void mma_tf32(float* c, const uint32_t* a, const uint32_t* b) {
    asm volatile(
        "mma.sync.aligned.m16n8k8.row.col.f32.tf32.tf32.f32 "
        "{%0,%1,%2,%3}, {%4,%5,%6,%7}, {%8,%9}, {%0,%1,%2,%3};"
        : "+f"(c[0]), "+f"(c[1]), "+f"(c[2]), "+f"(c[3])
        : "r"(a[0]), "r"(a[1]), "r"(a[2]), "r"(a[3]), "r"(b[0]), "r"(b[1]));
}

// ======================= tensor-core GEMM =======================
// C[bz] = act((A[bz][M,K] @ B[bz][K,N] + bias) / denom), split-tf32 (3 MMA terms).
// CTA tile 128x128, K-chunk 32, 256 threads (8 warps, 2x4 warp grid, 64x32 per warp).
// Double-buffered cp.async smem; 2 CTAs/SM (launch_bounds) so staging/sync of one CTA
// hides under the other's MMAs. Requires M%128==0, N%128==0, K%32==0.
#define APAD 36
#define BPAD 136
#define ASZ (128 * APAD)
#define BSZ (32 * BPAD)
#define TC_SMEM ((2 * ASZ + 2 * BSZ) * 4)

#define LOAD_CHUNK(cc, bb) do {                                                            \
    const float* Ac_ = Ag + (long long)(cc) * 32;                                          \
    const float* Bc_ = Bg + (long long)(cc) * 32 * N;                                      \
    const uint32_t ab_ = sbase + (bb) * (ASZ * 4);                                         \
    const uint32_t bbuf_ = sbase + (2 * ASZ + (bb) * BSZ) * 4;                             \
    _Pragma("unroll")                                                                      \
    for (int j_ = 0; j_ < 4; j_++) {                                                       \
        const int m_ = (tid >> 3) + j_ * 32;                                               \
        CP_ASYNC16(ab_ + (uint32_t)(m_ * APAD + (tid & 7) * 4) * 4,                        \
                   Ac_ + (long long)m_ * K + (tid & 7) * 4);                               \
    }                                                                                      \
    _Pragma("unroll")                                                                      \
    for (int j_ = 0; j_ < 4; j_++) {                                                       \
        const int k_ = (tid >> 5) + j_ * 8;                                                \
        CP_ASYNC16(bbuf_ + (uint32_t)(k_ * BPAD + (tid & 31) * 4) * 4,                     \
                   Bc_ + (long long)k_ * N + (tid & 31) * 4);                              \
    }                                                                                      \
    asm volatile("cp.async.commit_group;" ::: "memory");                                   \
} while (0)

template <int RELU, int DIV, int BIAS>
__global__ void __launch_bounds__(256, 2) tc_gemm(
    const float* __restrict__ A, const float* __restrict__ B,
    const float* __restrict__ bias, const float* __restrict__ denom,
    float* __restrict__ C, int N, int K,
    long long strA, long long strB, long long strC)
{
    extern __shared__ float smf[];
    const uint32_t sbase = smem_to_u32(smf);
    const int tid = threadIdx.x;
    const int lane = tid & 31, wid = tid >> 5;
    const int wm = wid & 1, wn = wid >> 1;     // warp grid 2 (M) x 4 (N)
    const int tig = lane & 3, gid = lane >> 2;
    const int row0 = blockIdx.y * 128, col0 = blockIdx.x * 128;
    const int bz = blockIdx.z;

    A += (long long)bz * strA;
    B += (long long)bz * strB;
    C += (long long)bz * strC;
    const float* Ag = A + (long long)row0 * K;
    const float* Bg = B + col0;

    const int nt = K >> 5;

    float acc[4][4][4];
#pragma unroll
    for (int i = 0; i < 4; i++)
#pragma unroll
        for (int j = 0; j < 4; j++)
#pragma unroll
            for (int r = 0; r < 4; r++) acc[i][j][r] = 0.f;

    LOAD_CHUNK(0, 0);

    for (int c = 0; c < nt; c++) {
        const int buf = c & 1;
        if (c + 1 < nt) {
            LOAD_CHUNK(c + 1, buf ^ 1);
            asm volatile("cp.async.wait_group 1;" ::: "memory");
        } else {
            asm volatile("cp.async.wait_group 0;" ::: "memory");
        }
        __syncthreads();

        const float* As = smf + buf * ASZ;
        const float* Bs = smf + 2 * ASZ + buf * BSZ;

#pragma unroll
        for (int kk = 0; kk < 4; kk++) {
            const int kb = kk * 8;
            uint32_t ah[4][4], al[4][4];
#pragma unroll
            for (int i = 0; i < 4; i++) {
                const int m = wm * 64 + i * 16 + gid;
                const float f0 = As[m * APAD + kb + tig];
                const float f1 = As[(m + 8) * APAD + kb + tig];
                const float f2 = As[m * APAD + kb + tig + 4];
                const float f3 = As[(m + 8) * APAD + kb + tig + 4];
                tf32_split(f0, ah[i][0], al[i][0]);
                tf32_split(f1, ah[i][1], al[i][1]);
                tf32_split(f2, ah[i][2], al[i][2]);
                tf32_split(f3, ah[i][3], al[i][3]);
            }
#pragma unroll
            for (int j = 0; j < 4; j++) {
                const int n = wn * 32 + j * 8 + gid;
                const float g0 = Bs[(kb + tig) * BPAD + n];
                const float g1 = Bs[(kb + tig + 4) * BPAD + n];
                uint32_t bh[2], bl[2];
                tf32_split(g0, bh[0], bl[0]);
                tf32_split(g1, bh[1], bl[1]);
#pragma unroll
                for (int i = 0; i < 4; i++) {
                    mma_tf32(acc[i][j], ah[i], bh);
                    mma_tf32(acc[i][j], ah[i], bl);
                    mma_tf32(acc[i][j], al[i], bh);
                }
            }
        }
        __syncthreads();
    }

    // epilogue
#pragma unroll
    for (int i = 0; i < 4; i++) {
        const int r0 = row0 + wm * 64 + i * 16 + gid;
        float inv0 = 1.f, inv1 = 1.f;
        if (DIV) { inv0 = 1.f / denom[r0]; inv1 = 1.f / denom[r0 + 8]; }
#pragma unroll
        for (int j = 0; j < 4; j++) {
            const int nc = col0 + wn * 32 + j * 8 + 2 * tig;
            float bx = 0.f, by = 0.f;
            if (BIAS) { const float2 bb = *(const float2*)(bias + nc); bx = bb.x; by = bb.y; }
            float o0 = acc[i][j][0] + bx, o1 = acc[i][j][1] + by;
            float o2 = acc[i][j][2] + bx, o3 = acc[i][j][3] + by;
            if (DIV) { o0 *= inv0; o1 *= inv0; o2 *= inv1; o3 *= inv1; }
            if (RELU) {
                o0 = fmaxf(o0, 0.f); o1 = fmaxf(o1, 0.f);
                o2 = fmaxf(o2, 0.f); o3 = fmaxf(o3, 0.f);
            }
            *(float2*)(C + (long long)r0 * N + nc) = make_float2(o0, o1);
            *(float2*)(C + (long long)(r0 + 8) * N + nc) = make_float2(o2, o3);
        }
    }
}

// ======================= fused attention (unchanged, proven) =======================
__global__ void __launch_bounds__(512, 2) attn_kernel(
    const float* __restrict__ qm, const float* __restrict__ km,
    const int* __restrict__ tok, const float* __restrict__ rel_emb,
    float* __restrict__ adj, float* __restrict__ denom)
{
    __shared__ __align__(16) float sQ[8][Dn];
    __shared__ __align__(16) float sQm[8][DKn];
    __shared__ float sR[8][257];
    __shared__ float sRed[16][8];
    __shared__ float sB[8];
    __shared__ int sTokQ[8];

    const int tid = threadIdx.x;
    const int b = blockIdx.x >> 6;
    const int q0 = (blockIdx.x & 63) * 8;
    const long long qbase = ((long long)b * Sn + q0) * Dn;

    for (int e = tid; e < 8 * Dn; e += 512) ((float*)sQ)[e] = qm[qbase + e];
    if (tid < 8) sTokQ[tid] = tok[b * Sn + q0 + tid];
    __syncthreads();

    for (int e = tid; e < 8 * DKn; e += 512) {
        const int qq = e / DKn, d = e % DKn;
        float s = 0.f;
#pragma unroll
        for (int h = 0; h < Hn; h++) s += sQ[qq][h * DKn + d];
        sQm[qq][d] = s * 0.125f;
    }
    __syncthreads();

    for (int e = tid; e < 8 * 257; e += 512) {
        const int qq = e / 257, j = e % 257;
        const float4* rp = (const float4*)(rel_emb + j * DKn);
        const float4* qp = (const float4*)sQm[qq];
        float s = 0.f;
#pragma unroll
        for (int d4 = 0; d4 < DKn / 4; d4++) {
            float4 rv = rp[d4], qv = qp[d4];
            s += rv.x * qv.x + rv.y * qv.y + rv.z * qv.z + rv.w * qv.w;
        }
        sR[qq][j] = s;
    }
    __syncthreads();

    const int kcol = tid;
    const bool kz = (tok[b * Sn + kcol] == 0);
    const float4* krow = (const float4*)(km + ((long long)b * Sn + kcol) * Dn);
    const float scale = 0.10206207261596577f;
    const int lane = tid & 31, wid = tid >> 5;

    float padj[8];
#pragma unroll
    for (int qq = 0; qq < 8; qq++) padj[qq] = 0.f;

    for (int h = 0; h < Hn; h++) {
        float sc[8];
#pragma unroll
        for (int qq = 0; qq < 8; qq++) sc[qq] = 0.f;
        const float4* kh = krow + h * (DKn / 4);
#pragma unroll
        for (int d4 = 0; d4 < DKn / 4; d4++) {
            const float4 kv = kh[d4];
#pragma unroll
            for (int qq = 0; qq < 8; qq++) {
                const float4 qv = *(const float4*)&sQ[qq][h * DKn + d4 * 4];
                sc[qq] += kv.x * qv.x + kv.y * qv.y + kv.z * qv.z + kv.w * qv.w;
            }
        }
#pragma unroll
        for (int qq = 0; qq < 8; qq++) {
            int dist = kcol - (q0 + qq);
            dist = min(max(dist, -128), 128) + 128;
            const float s = (sc[qq] + sR[qq][dist]) * scale;
            sc[qq] = kz ? -1e9f : s;
        }
        float red[8];
#pragma unroll
        for (int qq = 0; qq < 8; qq++) red[qq] = sc[qq];
#pragma unroll
        for (int off = 16; off > 0; off >>= 1)
#pragma unroll
            for (int qq = 0; qq < 8; qq++)
                red[qq] = fmaxf(red[qq], __shfl_xor_sync(0xffffffffu, red[qq], off));
        if (lane == 0)
#pragma unroll
            for (int qq = 0; qq < 8; qq++) sRed[wid][qq] = red[qq];
        __syncthreads();
        if (tid < 8) {
            float v = sRed[0][tid];
#pragma unroll
            for (int w = 1; w < 16; w++) v = fmaxf(v, sRed[w][tid]);
            sB[tid] = v;
        }
        __syncthreads();
        float ex[8];
#pragma unroll
        for (int qq = 0; qq < 8; qq++) ex[qq] = expf(sc[qq] - sB[qq]);
#pragma unroll
        for (int qq = 0; qq < 8; qq++) red[qq] = ex[qq];
#pragma unroll
        for (int off = 16; off > 0; off >>= 1)
#pragma unroll
            for (int qq = 0; qq < 8; qq++)
                red[qq] += __shfl_xor_sync(0xffffffffu, red[qq], off);
        if (lane == 0)
#pragma unroll
            for (int qq = 0; qq < 8; qq++) sRed[wid][qq] = red[qq];
        __syncthreads();
        if (tid < 8) {
            float v = 0.f;
#pragma unroll
            for (int w = 0; w < 16; w++) v += sRed[w][tid];
            sB[tid] = v;
        }
        __syncthreads();
#pragma unroll
        for (int qq = 0; qq < 8; qq++) padj[qq] += (ex[qq] / sB[qq]) * 0.125f;
        __syncthreads();
    }

    float rowv[8];
#pragma unroll
    for (int qq = 0; qq < 8; qq++) {
        float v = padj[qq];
        if (kcol == q0 + qq) v = 1.0f;
        if (sTokQ[qq] == 0) v = 0.0f;
        rowv[qq] = v;
        adj[((long long)b * Sn + q0 + qq) * Sn + kcol] = v;
    }
    float red[8];
#pragma unroll
    for (int qq = 0; qq < 8; qq++) red[qq] = rowv[qq];
#pragma unroll
    for (int off = 16; off > 0; off >>= 1)
#pragma unroll
        for (int qq = 0; qq < 8; qq++)
            red[qq] += __shfl_xor_sync(0xffffffffu, red[qq], off);
    if (lane == 0)
#pragma unroll
        for (int qq = 0; qq < 8; qq++) sRed[wid][qq] = red[qq];
    __syncthreads();
    if (tid < 8) {
        float v = 0.f;
#pragma unroll
        for (int w = 0; w < 16; w++) v += sRed[w][tid];
        denom[b * Sn + q0 + tid] = v + 1.0f;
    }
}

// ======================= small kernels =======================
__global__ void combine_kernel(const float* __restrict__ h0, const float* __restrict__ h1,
                               const float* __restrict__ sw, float* __restrict__ out)
{
    const int i = blockIdx.x * 256 + threadIdx.x;
    const float s0 = sw[0], s1 = sw[1];
    const float m = fmaxf(s0, s1);
    const float e0 = expf(s0 - m), e1 = expf(s1 - m);
    const float inv = 1.f / (e0 + e1);
    out[i] = (e0 * inv) * h0[i] + (e1 * inv) * h1[i];
}

__global__ void pool_kernel(const float* __restrict__ x, float* __restrict__ pool)
{
    const int b = blockIdx.y;
    const int d = blockIdx.x * 128 + threadIdx.x;
    const float* xp = x + (long long)b * Sn * Dn + d;
    float sm = 0.f, mx = -3.402823466e38f;
    for (int s = 0; s < Sn; s++) {
        const float v = xp[(long long)s * Dn];
        sm += v;
        mx = fmaxf(mx, v);
    }
    pool[b * (2 * Dn) + d] = sm * (1.f / Sn);
    pool[b * (2 * Dn) + Dn + d] = mx;
}

template <int ACT>
__global__ void rowmat_kernel(const float* __restrict__ in, const float* __restrict__ W,
                              const float* __restrict__ bias, float* __restrict__ out,
                              int K, int N)
{
    __shared__ float sIn[2 * Dn];
    const int b = blockIdx.y;
    const int n = blockIdx.x * 128 + threadIdx.x;
    for (int e = threadIdx.x; e < K; e += 128) sIn[e] = in[b * K + e];
    __syncthreads();
    float acc = bias[n];
#pragma unroll 4
    for (int k = 0; k < K; k++) acc += sIn[k] * W[(long long)k * N + n];
    if (ACT) acc = 1.f / (1.f + expf(-acc));
    out[b * N + n] = acc;
}

__global__ void final_kernel(float* __restrict__ x, const float* __restrict__ gate,
                             const float* __restrict__ gc)
{
    const int i = blockIdx.x * 256 + threadIdx.x;
    const int d = i % Dn;
    const int b = i / (Sn * Dn);
    x[i] += gate[b * Dn + d] * gc[b * Dn + d];
}

// ======================= launch =======================
extern "C" void kernel_launch(void* const* d_in, const int* in_sizes, int n_in,
                              void* d_out, int out_size)
{
    int o = (n_in >= 3 && in_sizes[2] == 1) ? 1 : 0;
    const float* inputs = (const float*)d_in[0];
    const int*   tok    = (const int*)d_in[1];
    const float* Wq  = (const float*)d_in[2 + o];
    const float* bq  = (const float*)d_in[3 + o];
    const float* Wk  = (const float*)d_in[4 + o];
    const float* bk  = (const float*)d_in[5 + o];
    const float* rel = (const float*)d_in[6 + o];
    const float* W0  = (const float*)d_in[7 + o];
    const float* b0  = (const float*)d_in[8 + o];
    const float* W1  = (const float*)d_in[9 + o];
    const float* b1  = (const float*)d_in[10 + o];
    const float* scw = (const float*)d_in[11 + o];
    const float* Wf  = (const float*)d_in[12 + o];
    const float* bf  = (const float*)d_in[13 + o];
    const float* Wfc = (const float*)d_in[14 + o];
    const float* bfc = (const float*)d_in[15 + o];
    const float* Wg  = (const float*)d_in[16 + o];
    const float* bg  = (const float*)d_in[17 + o];

    float* out = (float*)d_out;                      // (B,S,D)
    float* adj = out + (size_t)Bn * Sn * Dn;         // (B,S,S)

    float *q, *k, *ax, *h0, *h1, *den, *pool, *gc, *gate;
    cudaGetSymbolAddress((void**)&q, g_q);
    cudaGetSymbolAddress((void**)&k, g_k);
    cudaGetSymbolAddress((void**)&ax, g_ax);
    cudaGetSymbolAddress((void**)&h0, g_h0);
    cudaGetSymbolAddress((void**)&h1, g_h1);
    cudaGetSymbolAddress((void**)&den, g_denom);
    cudaGetSymbolAddress((void**)&pool, g_pool);
    cudaGetSymbolAddress((void**)&gc, g_gc);
    cudaGetSymbolAddress((void**)&gate, g_gate);

    cudaFuncSetAttribute(tc_gemm<0, 0, 1>, cudaFuncAttributeMaxDynamicSharedMemorySize, TC_SMEM);
    cudaFuncSetAttribute(tc_gemm<0, 0, 0>, cudaFuncAttributeMaxDynamicSharedMemorySize, TC_SMEM);
    cudaFuncSetAttribute(tc_gemm<1, 1, 1>, cudaFuncAttributeMaxDynamicSharedMemorySize, TC_SMEM);

    const dim3 gFlat(Dn / 128, (Bn * Sn) / 128, 1);  // 6 x 64
    const dim3 gBmm(Dn / 128, Sn / 128, Bn);         // 6 x 4 x 16
    const int nElem = Bn * Sn * Dn;

    // Q/K projections
    tc_gemm<0, 0, 1><<<gFlat, 256, TC_SMEM>>>(inputs, Wq, bq, nullptr, q, Dn, Dn, 0, 0, 0);
    tc_gemm<0, 0, 1><<<gFlat, 256, TC_SMEM>>>(inputs, Wk, bk, nullptr, k, Dn, Dn, 0, 0, 0);

    // fused attention -> adj, denom
    attn_kernel<<<Bn * (Sn / 8), 512>>>(q, k, tok, rel, adj, den);

    // GCN layer 0
    tc_gemm<0, 0, 0><<<gBmm, 256, TC_SMEM>>>(adj, inputs, nullptr, nullptr, ax, Dn, Sn,
                                             (long long)Sn * Sn, (long long)Sn * Dn,
                                             (long long)Sn * Dn);
    tc_gemm<1, 1, 1><<<gFlat, 256, TC_SMEM>>>(ax, W0, b0, den, h0, Dn, Dn, 0, 0, 0);

    // GCN layer 1
    tc_gemm<0, 0, 0><<<gBmm, 256, TC_SMEM>>>(adj, h0, nullptr, nullptr, ax, Dn, Sn,
                                             (long long)Sn * Sn, (long long)Sn * Dn,
                                             (long long)Sn * Dn);
    tc_gemm<1, 1, 1><<<gFlat, 256, TC_SMEM>>>(ax, W1, b1, den, h1, Dn, Dn, 0, 0, 0);

    // fusion + Wf -> out
    combine_kernel<<<nElem / 256, 256>>>(h0, h1, scw, ax);
    tc_gemm<0, 0, 1><<<gFlat, 256, TC_SMEM>>>(ax, Wf, bf, nullptr, out, Dn, Dn, 0, 0, 0);

    // global context gating
    pool_kernel<<<dim3(Dn / 128, Bn), 128>>>(out, pool);
    rowmat_kernel<0><<<dim3(Dn / 128, Bn), 128>>>(pool, Wfc, bfc, gc, 2 * Dn, Dn);
    rowmat_kernel<1><<<dim3(Dn / 128, Bn), 128>>>(gc, Wg, bg, gate, Dn, Dn);
    final_kernel<<<(Bn * Sn * Dn) / 256, 256>>>(out, gate, gc);
}